// round 2
// baseline (speedup 1.0000x reference)
#include <cuda_runtime.h>
#include <stdint.h>

#define N_PTS 16384
#define TPB 256
#define PTS_PER_THREAD 2
#define J_TILE 2048
#define J_SPLITS (N_PTS / J_TILE)                    // 8
#define I_BLOCKS (N_PTS / (TPB * PTS_PER_THREAD))    // 32

// Scratch: per-point min squared distance, as uint bits (all values >= 0 so
// uint ordering == float ordering). [0] = per-prediction min, [1] = per-gt min.
__device__ unsigned int g_min_sq[2][N_PTS];

__global__ void cd_init_kernel() {
    int i = blockIdx.x * blockDim.x + threadIdx.x;
    if (i < 2 * N_PTS) ((unsigned int*)g_min_sq)[i] = 0x7F800000u; // +inf
}

__global__ void __launch_bounds__(TPB) cd_pass_kernel(
    const float* __restrict__ pred, const float* __restrict__ gt)
{
    // blockIdx.z = 0: query = pred, database = gt
    // blockIdx.z = 1: query = gt,   database = pred
    const float* __restrict__ A = (blockIdx.z == 0) ? pred : gt;
    const float* __restrict__ B = (blockIdx.z == 0) ? gt : pred;

    __shared__ float4 tile[J_TILE];   // (x, y, z, 0.5*|b|^2)

    const int jbase = blockIdx.y * J_TILE;
    for (int p = threadIdx.x; p < J_TILE; p += TPB) {
        int j = jbase + p;
        float x = B[3 * j + 0];
        float y = B[3 * j + 1];
        float z = B[3 * j + 2];
        float c = 0.5f * (x * x + y * y + z * z);
        tile[p] = make_float4(x, y, z, c);
    }
    __syncthreads();

    // Two query points per thread: amortize the shared-mem broadcast load.
    const int i0 = (blockIdx.x * TPB + threadIdx.x) * PTS_PER_THREAD;
    const float a0x = A[3 * i0 + 0];
    const float a0y = A[3 * i0 + 1];
    const float a0z = A[3 * i0 + 2];
    const float a1x = A[3 * i0 + 3];
    const float a1y = A[3 * i0 + 4];
    const float a1z = A[3 * i0 + 5];

    // min_j ||a - b_j||^2 = |a|^2 - 2 * max_j ( a.b_j - 0.5*|b_j|^2 )
    float best0 = -3.402823466e+38f;
    float best1 = -3.402823466e+38f;
#pragma unroll 8
    for (int p = 0; p < J_TILE; ++p) {
        float4 b = tile[p];
        float t0 = fmaf(a0x, b.x, -b.w);
        float t1 = fmaf(a1x, b.x, -b.w);
        t0 = fmaf(a0y, b.y, t0);
        t1 = fmaf(a1y, b.y, t1);
        t0 = fmaf(a0z, b.z, t0);
        t1 = fmaf(a1z, b.z, t1);
        best0 = fmaxf(best0, t0);
        best1 = fmaxf(best1, t1);
    }

    float a02 = fmaf(a0x, a0x, fmaf(a0y, a0y, a0z * a0z));
    float a12 = fmaf(a1x, a1x, fmaf(a1y, a1y, a1z * a1z));
    float sq0 = fmaxf(fmaf(-2.0f, best0, a02), 0.0f);
    float sq1 = fmaxf(fmaf(-2.0f, best1, a12), 0.0f);
    atomicMin(&g_min_sq[blockIdx.z][i0],     __float_as_uint(sq0));
    atomicMin(&g_min_sq[blockIdx.z][i0 + 1], __float_as_uint(sq1));
}

__global__ void cd_reduce_kernel(float* __restrict__ out) {
    __shared__ float ssum[TPB / 32];
    float s = 0.0f;
    const unsigned int* m = (const unsigned int*)g_min_sq;
    for (int i = threadIdx.x; i < 2 * N_PTS; i += TPB)
        s += sqrtf(__uint_as_float(m[i]));

    // warp reduce
    for (int o = 16; o > 0; o >>= 1)
        s += __shfl_xor_sync(0xFFFFFFFFu, s, o);
    if ((threadIdx.x & 31) == 0) ssum[threadIdx.x >> 5] = s;
    __syncthreads();

    if (threadIdx.x == 0) {
        float tot = 0.0f;
        for (int w = 0; w < TPB / 32; ++w) tot += ssum[w];
        out[0] = tot / (float)N_PTS;   // (sum1 + sum2)/N = mean1 + mean2
    }
}

extern "C" void kernel_launch(void* const* d_in, const int* in_sizes, int n_in,
                              void* d_out, int out_size) {
    const float* pred = (const float*)d_in[0];
    const float* gt   = (const float*)d_in[1];
    float* out = (float*)d_out;

    cd_init_kernel<<<(2 * N_PTS + 255) / 256, 256>>>();
    dim3 grid(I_BLOCKS, J_SPLITS, 2);
    cd_pass_kernel<<<grid, TPB>>>(pred, gt);
    cd_reduce_kernel<<<1, TPB>>>(out);
}

// round 3
// speedup vs baseline: 1.7344x; 1.7344x over previous
#include <cuda_runtime.h>
#include <stdint.h>

#define N_PTS 16384
#define TPB 256
#define QPT 4                              // query points per thread
#define J_TILE 256                         // db points per block tile
#define J_SPLITS (N_PTS / J_TILE)          // 64
#define I_BLOCKS (N_PTS / (TPB * QPT))     // 16
#define R1_BLOCKS 128

// Partial results: max_j (a.b_j - 0.5|b_j|^2) per (direction, j-split, point).
// Every slot written exactly once by its block -> no init, no atomics.
__device__ float g_part[2][J_SPLITS][N_PTS];   // 8 MB
__device__ float g_bsum[R1_BLOCKS];

__device__ __forceinline__ unsigned long long pack2(float lo, float hi) {
    unsigned long long r;
    asm("mov.b64 %0, {%1, %2};" : "=l"(r) : "f"(lo), "f"(hi));
    return r;
}
__device__ __forceinline__ unsigned long long fma2(
    unsigned long long a, unsigned long long b, unsigned long long c) {
    unsigned long long d;
    asm("fma.rn.f32x2 %0, %1, %2, %3;" : "=l"(d) : "l"(a), "l"(b), "l"(c));
    return d;
}
__device__ __forceinline__ void unpack2(unsigned long long v, float& lo, float& hi) {
    asm("mov.b64 {%0, %1}, %2;" : "=f"(lo), "=f"(hi) : "l"(v));
}

__global__ void __launch_bounds__(TPB) cd_pass_kernel(
    const float* __restrict__ pred, const float* __restrict__ gt)
{
    // z=0: query=pred, db=gt; z=1: query=gt, db=pred
    const float* __restrict__ A = (blockIdx.z == 0) ? pred : gt;
    const float* __restrict__ B = (blockIdx.z == 0) ? gt : pred;

    // db tile, 2 points packed per entry: (x0,x1),(y0,y1) and (z0,z1),(c0,c1)
    // with c = -0.5*|b|^2 (negated so it drops straight into the first fma).
    __shared__ ulonglong2 tile_xy[J_TILE / 2];
    __shared__ ulonglong2 tile_zc[J_TILE / 2];

    const int t = threadIdx.x;
    const int jbase = blockIdx.y * J_TILE;
    if (t < J_TILE / 2) {
        const float* bp = B + 3 * (jbase + 2 * t);
        float x0 = bp[0], y0 = bp[1], z0 = bp[2];
        float x1 = bp[3], y1 = bp[4], z1 = bp[5];
        float c0 = -0.5f * fmaf(x0, x0, fmaf(y0, y0, z0 * z0));
        float c1 = -0.5f * fmaf(x1, x1, fmaf(y1, y1, z1 * z1));
        tile_xy[t] = make_ulonglong2(pack2(x0, x1), pack2(y0, y1));
        tile_zc[t] = make_ulonglong2(pack2(z0, z1), pack2(c0, c1));
    }

    // 4 query points per thread, broadcast-packed (a,a) once.
    const int i0 = (blockIdx.x * TPB + t) * QPT;
    const float4 qa = *(const float4*)(A + 3 * i0);
    const float4 qb = *(const float4*)(A + 3 * i0 + 4);
    const float4 qc = *(const float4*)(A + 3 * i0 + 8);

    unsigned long long qx[QPT], qy[QPT], qz[QPT];
    qx[0] = pack2(qa.x, qa.x); qy[0] = pack2(qa.y, qa.y); qz[0] = pack2(qa.z, qa.z);
    qx[1] = pack2(qa.w, qa.w); qy[1] = pack2(qb.x, qb.x); qz[1] = pack2(qb.y, qb.y);
    qx[2] = pack2(qb.z, qb.z); qy[2] = pack2(qb.w, qb.w); qz[2] = pack2(qc.x, qc.x);
    qx[3] = pack2(qc.y, qc.y); qy[3] = pack2(qc.z, qc.z); qz[3] = pack2(qc.w, qc.w);

    float best0[QPT], best1[QPT];
#pragma unroll
    for (int q = 0; q < QPT; ++q) { best0[q] = -3.402823466e+38f; best1[q] = -3.402823466e+38f; }

    __syncthreads();

    // min_j ||a-b_j||^2 = |a|^2 - 2 * max_j (a.b_j - 0.5|b_j|^2)
#pragma unroll 4
    for (int p = 0; p < J_TILE / 2; ++p) {
        const ulonglong2 xy = tile_xy[p];   // LDS.128 broadcast
        const ulonglong2 zc = tile_zc[p];   // LDS.128 broadcast
#pragma unroll
        for (int q = 0; q < QPT; ++q) {
            unsigned long long tt = fma2(qx[q], xy.x, zc.y);
            tt = fma2(qy[q], xy.y, tt);
            tt = fma2(qz[q], zc.x, tt);
            float t0, t1;
            unpack2(tt, t0, t1);            // reg-pair aliasing, free in SASS
            best0[q] = fmaxf(best0[q], t0);
            best1[q] = fmaxf(best1[q], t1);
        }
    }

    float4 outv;
    outv.x = fmaxf(best0[0], best1[0]);
    outv.y = fmaxf(best0[1], best1[1]);
    outv.z = fmaxf(best0[2], best1[2]);
    outv.w = fmaxf(best0[3], best1[3]);
    *(float4*)&g_part[blockIdx.z][blockIdx.y][i0] = outv;
}

__global__ void __launch_bounds__(TPB) cd_reduce1_kernel(
    const float* __restrict__ pred, const float* __restrict__ gt)
{
    const int gidx = blockIdx.x * TPB + threadIdx.x;   // 0 .. 32767
    const int z = gidx >> 14;
    const int i = gidx & (N_PTS - 1);

    float m = -3.402823466e+38f;
#pragma unroll 8
    for (int j = 0; j < J_SPLITS; ++j) m = fmaxf(m, g_part[z][j][i]);

    const float* __restrict__ A = (z == 0) ? pred : gt;
    const float ax = A[3 * i], ay = A[3 * i + 1], az = A[3 * i + 2];
    const float a2 = fmaf(ax, ax, fmaf(ay, ay, az * az));
    float s = sqrtf(fmaxf(fmaf(-2.0f, m, a2), 0.0f));

    // block sum
    __shared__ float ssum[TPB / 32];
    for (int o = 16; o > 0; o >>= 1) s += __shfl_xor_sync(0xFFFFFFFFu, s, o);
    if ((threadIdx.x & 31) == 0) ssum[threadIdx.x >> 5] = s;
    __syncthreads();
    if (threadIdx.x == 0) {
        float tot = 0.0f;
        for (int w = 0; w < TPB / 32; ++w) tot += ssum[w];
        g_bsum[blockIdx.x] = tot;
    }
}

__global__ void cd_reduce2_kernel(float* __restrict__ out) {
    float s = g_bsum[threadIdx.x];   // 128 threads, 128 partials
    for (int o = 16; o > 0; o >>= 1) s += __shfl_xor_sync(0xFFFFFFFFu, s, o);
    __shared__ float ssum[4];
    if ((threadIdx.x & 31) == 0) ssum[threadIdx.x >> 5] = s;
    __syncthreads();
    if (threadIdx.x == 0) {
        float tot = ssum[0] + ssum[1] + ssum[2] + ssum[3];
        out[0] = tot / (float)N_PTS;   // (sum1 + sum2)/N = mean1 + mean2
    }
}

extern "C" void kernel_launch(void* const* d_in, const int* in_sizes, int n_in,
                              void* d_out, int out_size) {
    const float* pred = (const float*)d_in[0];
    const float* gt   = (const float*)d_in[1];
    float* out = (float*)d_out;

    dim3 grid(I_BLOCKS, J_SPLITS, 2);          // (16, 64, 2) = 2048 blocks
    cd_pass_kernel<<<grid, TPB>>>(pred, gt);
    cd_reduce1_kernel<<<R1_BLOCKS, TPB>>>(pred, gt);
    cd_reduce2_kernel<<<1, 128>>>(out);
}

// round 5
// speedup vs baseline: 1.7556x; 1.0123x over previous
#include <cuda_runtime.h>
#include <stdint.h>

#define N_PTS 16384
#define TPB 256
#define QPT 4                              // query points per thread
#define J_TILE 128                         // db points per block tile
#define J_SPLITS (N_PTS / J_TILE)          // 128
#define I_BLOCKS (N_PTS / (TPB * QPT))     // 16
#define R1_BLOCKS 128

// Partial results: max_j (a.b_j - 0.5|b_j|^2) per (direction, j-split, point).
// Every slot written exactly once by its block -> no init, no atomics.
__device__ float g_part[2][J_SPLITS][N_PTS];   // 16 MB (L2-resident)
__device__ float g_bsum[R1_BLOCKS];

__device__ __forceinline__ unsigned long long pack2(float lo, float hi) {
    unsigned long long r;
    asm("mov.b64 %0, {%1, %2};" : "=l"(r) : "f"(lo), "f"(hi));
    return r;
}
__device__ __forceinline__ unsigned long long fma2(
    unsigned long long a, unsigned long long b, unsigned long long c) {
    unsigned long long d;
    asm("fma.rn.f32x2 %0, %1, %2, %3;" : "=l"(d) : "l"(a), "l"(b), "l"(c));
    return d;
}
__device__ __forceinline__ void unpack2(unsigned long long v, float& lo, float& hi) {
    asm("mov.b64 {%0, %1}, %2;" : "=f"(lo), "=f"(hi) : "l"(v));
}

__global__ void __launch_bounds__(TPB, 5) cd_pass_kernel(
    const float* __restrict__ pred, const float* __restrict__ gt)
{
    // z=0: query=pred, db=gt; z=1: query=gt, db=pred
    const float* __restrict__ A = (blockIdx.z == 0) ? pred : gt;
    const float* __restrict__ B = (blockIdx.z == 0) ? gt : pred;

    // db tile, 2 points packed per entry: (x0,x1),(y0,y1) and (z0,z1),(c0,c1)
    // with c = -0.5*|b|^2 (negated so it drops straight into the first fma).
    __shared__ ulonglong2 tile_xy[J_TILE / 2];
    __shared__ ulonglong2 tile_zc[J_TILE / 2];

    const int t = threadIdx.x;
    const int jbase = blockIdx.y * J_TILE;
    if (t < J_TILE / 2) {
        const float* bp = B + 3 * (jbase + 2 * t);
        float x0 = bp[0], y0 = bp[1], z0 = bp[2];
        float x1 = bp[3], y1 = bp[4], z1 = bp[5];
        float c0 = -0.5f * fmaf(x0, x0, fmaf(y0, y0, z0 * z0));
        float c1 = -0.5f * fmaf(x1, x1, fmaf(y1, y1, z1 * z1));
        tile_xy[t] = make_ulonglong2(pack2(x0, x1), pack2(y0, y1));
        tile_zc[t] = make_ulonglong2(pack2(z0, z1), pack2(c0, c1));
    }

    // 4 query points per thread, broadcast-packed (a,a) once.
    const int i0 = (blockIdx.x * TPB + t) * QPT;
    const float4 qa = *(const float4*)(A + 3 * i0);
    const float4 qb = *(const float4*)(A + 3 * i0 + 4);
    const float4 qc = *(const float4*)(A + 3 * i0 + 8);

    unsigned long long qx[QPT], qy[QPT], qz[QPT];
    qx[0] = pack2(qa.x, qa.x); qy[0] = pack2(qa.y, qa.y); qz[0] = pack2(qa.z, qa.z);
    qx[1] = pack2(qa.w, qa.w); qy[1] = pack2(qb.x, qb.x); qz[1] = pack2(qb.y, qb.y);
    qx[2] = pack2(qb.z, qb.z); qy[2] = pack2(qb.w, qb.w); qz[2] = pack2(qc.x, qc.x);
    qx[3] = pack2(qc.y, qc.y); qy[3] = pack2(qc.z, qc.z); qz[3] = pack2(qc.w, qc.w);

    float best0[QPT], best1[QPT];
#pragma unroll
    for (int q = 0; q < QPT; ++q) { best0[q] = -3.402823466e+38f; best1[q] = -3.402823466e+38f; }

    __syncthreads();

    // min_j ||a-b_j||^2 = |a|^2 - 2 * max_j (a.b_j - 0.5|b_j|^2)
#pragma unroll 8
    for (int p = 0; p < J_TILE / 2; ++p) {
        const ulonglong2 xy = tile_xy[p];   // LDS.128 broadcast
        const ulonglong2 zc = tile_zc[p];   // LDS.128 broadcast
#pragma unroll
        for (int q = 0; q < QPT; ++q) {
            unsigned long long tt = fma2(qx[q], xy.x, zc.y);
            tt = fma2(qy[q], xy.y, tt);
            tt = fma2(qz[q], zc.x, tt);
            float t0, t1;
            unpack2(tt, t0, t1);            // reg-pair aliasing, free in SASS
            best0[q] = fmaxf(best0[q], t0);
            best1[q] = fmaxf(best1[q], t1);
        }
    }

    float4 outv;
    outv.x = fmaxf(best0[0], best1[0]);
    outv.y = fmaxf(best0[1], best1[1]);
    outv.z = fmaxf(best0[2], best1[2]);
    outv.w = fmaxf(best0[3], best1[3]);
    *(float4*)&g_part[blockIdx.z][blockIdx.y][i0] = outv;
}

__global__ void __launch_bounds__(TPB) cd_reduce1_kernel(
    const float* __restrict__ pred, const float* __restrict__ gt)
{
    const int gidx = blockIdx.x * TPB + threadIdx.x;   // 0 .. 32767
    const int z = gidx >> 14;
    const int i = gidx & (N_PTS - 1);

    float m = -3.402823466e+38f;
#pragma unroll 16
    for (int j = 0; j < J_SPLITS; ++j) m = fmaxf(m, g_part[z][j][i]);

    const float* __restrict__ A = (z == 0) ? pred : gt;
    const float ax = A[3 * i], ay = A[3 * i + 1], az = A[3 * i + 2];
    const float a2 = fmaf(ax, ax, fmaf(ay, ay, az * az));
    float s = sqrtf(fmaxf(fmaf(-2.0f, m, a2), 0.0f));

    // block sum
    __shared__ float ssum[TPB / 32];
    for (int o = 16; o > 0; o >>= 1) s += __shfl_xor_sync(0xFFFFFFFFu, s, o);
    if ((threadIdx.x & 31) == 0) ssum[threadIdx.x >> 5] = s;
    __syncthreads();
    if (threadIdx.x == 0) {
        float tot = 0.0f;
        for (int w = 0; w < TPB / 32; ++w) tot += ssum[w];
        g_bsum[blockIdx.x] = tot;
    }
}

__global__ void cd_reduce2_kernel(float* __restrict__ out) {
    float s = g_bsum[threadIdx.x];   // 128 threads, 128 partials
    for (int o = 16; o > 0; o >>= 1) s += __shfl_xor_sync(0xFFFFFFFFu, s, o);
    __shared__ float ssum[4];
    if ((threadIdx.x & 31) == 0) ssum[threadIdx.x >> 5] = s;
    __syncthreads();
    if (threadIdx.x == 0) {
        float tot = ssum[0] + ssum[1] + ssum[2] + ssum[3];
        out[0] = tot / (float)N_PTS;   // (sum1 + sum2)/N = mean1 + mean2
    }
}

extern "C" void kernel_launch(void* const* d_in, const int* in_sizes, int n_in,
                              void* d_out, int out_size) {
    const float* pred = (const float*)d_in[0];
    const float* gt   = (const float*)d_in[1];
    float* out = (float*)d_out;

    dim3 grid(I_BLOCKS, J_SPLITS, 2);          // (16, 128, 2) = 4096 blocks
    cd_pass_kernel<<<grid, TPB>>>(pred, gt);
    cd_reduce1_kernel<<<R1_BLOCKS, TPB>>>(pred, gt);
    cd_reduce2_kernel<<<1, 128>>>(out);
}